// round 9
// baseline (speedup 1.0000x reference)
#include <cuda_runtime.h>
#include <cstdint>

#define HID   32
#define NCOL  224
#define NSTEP 2047
#define NB    512
#define SEQ   2048
#define NTY   20
#define BETA  0.1f

typedef unsigned long long ull;

__device__ __forceinline__ unsigned su32(const void* p) {
    return (unsigned)__cvta_generic_to_shared(p);
}
__device__ __forceinline__ void ffma2(ull& d, ull a, ull b) {
    asm("fma.rn.f32x2 %0, %1, %2, %0;" : "+l"(d) : "l"(a), "l"(b));
}
__device__ __forceinline__ ull fadd2(ull a, ull b) {
    ull d; asm("add.rn.f32x2 %0, %1, %2;" : "=l"(d) : "l"(a), "l"(b)); return d;
}
__device__ __forceinline__ ull pack2(float a, float b) {
    ull d; asm("mov.b64 %0, {%1, %2};" : "=l"(d) : "f"(a), "f"(b)); return d;
}
__device__ __forceinline__ float sum2(ull v) {
    float a, b; asm("mov.b64 {%0, %1}, %2;" : "=f"(a), "=f"(b) : "l"(v));
    return a + b;
}
__device__ __forceinline__ void lds128(ull& a, ull& b, unsigned addr) {
    asm volatile("ld.shared.v2.u64 {%0, %1}, [%2];" : "=l"(a), "=l"(b) : "r"(addr));
}

__device__ __forceinline__ float tanh_fast(float x) {
    float e = __expf(-2.f * fabsf(x));          // overflow-safe: e in (0,1]
    float t = __fdividef(1.f - e, 1.f + e);
    return copysignf(t, x);
}
__device__ __forceinline__ float sigmoid_fast(float x) {
    return __fdividef(1.f, 1.f + __expf(-x));
}

__global__ __launch_bounds__(64, 4)
void hawkes_kernel(const int* __restrict__ types,
                   const float* __restrict__ dtime,
                   const float* __restrict__ emb,
                   const float* __restrict__ W,
                   const float* __restrict__ bvec,
                   float* __restrict__ out)
{
    // per-lane gx tables: gx0[ty][l] = {i,f,z,o} cols, gx1[ty][l] = {ib,fb,delta,-}
    __shared__ __align__(16) float4 s_gx0[NTY][HID];
    __shared__ __align__(16) float4 s_gx1[NTY][HID];
    __shared__ __align__(16) float  s_h[2][HID];        // warp-private h
    __shared__ __align__(16) float4 s_x0[2][HID];       // warp0 -> warp1: (i,f,z,o), dbl-buf
    __shared__ __align__(16) float4 s_x1[2][HID];       // warp1 -> warp0: (ib,fb,edt,-)
    __shared__ float s_emb[NTY * HID];
    __shared__ unsigned char s_ty[NSTEP + 1];
    __shared__ float s_dt[NSTEP];

    const int tid  = threadIdx.x;
    const int warp = tid >> 5;          // 0 or 1
    const int lane = tid & 31;
    const int bs   = blockIdx.x;

    // ---- prologue ----
    for (int i = tid; i < NTY * HID; i += 64) s_emb[i] = emb[i];
    for (int t = tid; t < NSTEP; t += 64) {
        s_ty[t] = (unsigned char)types[bs * SEQ + t];
        s_dt[t] = dtime[bs * SEQ + t + 1];
    }
    s_h[warp][lane] = 0.f;
    __syncthreads();

    // this thread's columns: gate j*... warp0: gates 0..3, warp1: gates 4..6
    const int NC   = (warp == 0) ? 4 : 3;
    const int g0   = warp * 4;                   // first gate index
    // build gx tables (x-side contribution + bias), per lane
    {
        float acc[4];
        for (int ty = 0; ty < NTY; ty++) {
            #pragma unroll
            for (int j = 0; j < 4; j++) acc[j] = 0.f;
            for (int j = 0; j < NC; j++) {
                const int c = (g0 + j) * HID + lane;
                float a = bvec[c];
                for (int k = 0; k < HID; k++) a += s_emb[ty * HID + k] * W[k * NCOL + c];
                acc[j] = a;
            }
            float4 v = make_float4(acc[0], acc[1], acc[2], acc[3]);
            if (warp == 0) s_gx0[ty][lane] = v; else s_gx1[ty][lane] = v;
        }
    }
    // recurrent weights, k-packed: w[j][q] = {W_h[2q][c_j], W_h[2q+1][c_j]}
    ull w[4][16];
    for (int j = 0; j < NC; j++) {
        const int c = (g0 + j) * HID + lane;
        #pragma unroll
        for (int q = 0; q < 16; q++)
            w[j][q] = pack2(W[(HID + 2 * q) * NCOL + c],
                            W[(HID + 2 * q + 1) * NCOL + c]);
    }
    __syncthreads();

    const unsigned hb = su32(&s_h[warp][0]);
    float c = 0.f, cbar = 0.f;                   // replicated in both warps

    const size_t O1 = (size_t)NSTEP * NB * HID;
    size_t obase = (size_t)bs * HID + lane;

    #pragma unroll 2
    for (int t = 0; t < NSTEP; t++) {
        const int ty = s_ty[t];
        const int buf = t & 1;

        // matvec: 8 broadcast LDS.128 feed all columns (packed fp32x2)
        ull acc0[4], acc1[4];
        #pragma unroll
        for (int j = 0; j < 4; j++) { acc0[j] = 0; acc1[j] = 0; }
        #pragma unroll
        for (int q = 0; q < 8; q++) {
            ull hA, hB;
            lds128(hA, hB, hb + q * 16);
            if (warp == 0) {
                #pragma unroll
                for (int j = 0; j < 4; j++) {
                    ffma2(acc0[j], hA, w[j][2 * q]);
                    ffma2(acc1[j], hB, w[j][2 * q + 1]);
                }
            } else {
                #pragma unroll
                for (int j = 0; j < 3; j++) {
                    ffma2(acc0[j], hA, w[j][2 * q]);
                    ffma2(acc1[j], hB, w[j][2 * q + 1]);
                }
            }
        }

        float ig, fg, zg, og, ibg, fbg, edt;
        if (warp == 0) {
            const float4 gx = s_gx0[ty][lane];
            ig = sigmoid_fast(gx.x + sum2(fadd2(acc0[0], acc1[0])));
            fg = sigmoid_fast(gx.y + sum2(fadd2(acc0[1], acc1[1])));
            zg = tanh_fast   (gx.z + sum2(fadd2(acc0[2], acc1[2])));
            og = sigmoid_fast(gx.w + sum2(fadd2(acc0[3], acc1[3])));
            s_x0[buf][lane] = make_float4(ig, fg, zg, og);
        } else {
            const float4 gx = s_gx1[ty][lane];
            ibg = sigmoid_fast(gx.x + sum2(fadd2(acc0[0], acc1[0])));
            fbg = sigmoid_fast(gx.y + sum2(fadd2(acc0[1], acc1[1])));
            const float gd = gx.z + sum2(fadd2(acc0[2], acc1[2]));
            const float y  = BETA * gd;
            const float del = (fmaxf(y, 0.f) + __logf(1.f + __expf(-fabsf(y)))) * (1.f / BETA);
            out[3 * O1 + obase] = del;                    // decay_out
            edt = __expf(-del * s_dt[t]);
            s_x1[buf][lane] = make_float4(ibg, fbg, edt, 0.f);
        }
        __syncthreads();                                  // the only block barrier per step

        // exchange + redundant lane-local combine (bitwise identical in both warps)
        if (warp == 0) {
            const float4 p = s_x1[buf][lane];
            ibg = p.x; fbg = p.y; edt = p.z;
        } else {
            const float4 p = s_x0[buf][lane];
            ig = p.x; fg = p.y; zg = p.z; og = p.w;
        }
        const float cn  = fmaf(fg, c, ig * zg);
        const float cbn = fmaf(fbg, cbar, ibg * zg);
        const float ct  = fmaf(cn - cbn, edt, cbn);
        const float hn  = og * tanh_fast(ct);
        c = ct; cbar = cbn;

        s_h[warp][lane] = hn;                             // warp-private, no block sync needed
        __syncwarp();

        if (warp == 0) {
            out[obase]          = hn;                     // h_out
            out[O1 + obase]     = cn;                     // c_out
        } else {
            out[2 * O1 + obase] = cbn;                    // c_bar_out
            out[4 * O1 + obase] = og;                     // gate_out
        }
        obase += (size_t)NB * HID;
    }
}

extern "C" void kernel_launch(void* const* d_in, const int* in_sizes, int n_in,
                              void* d_out, int out_size)
{
    const int*   types = (const int*)d_in[0];
    const float* dtime = (const float*)d_in[1];
    const float* emb   = (const float*)d_in[2];
    const float* W     = (const float*)d_in[3];
    const float* bvec  = (const float*)d_in[4];
    hawkes_kernel<<<NB, 64>>>(types, dtime, emb, W, bvec, (float*)d_out);
}